// round 4
// baseline (speedup 1.0000x reference)
#include <cuda_runtime.h>
#include <math.h>

// Problem constants (fixed-shape problem):
//   B = 2048 batch rows, N = 4095 points per row.
// Inputs (metadata order):
//   d_in[0] origin_3D          (B,3,1)
//   d_in[1] spherical_3D       (B,3,N)
//   d_in[2] origin_2D          (B,3,1)
//   d_in[3] spherical_2D       (B,3,N)
//   d_in[4] deformation_field  (B,2,N)
// Output: scalar float32.
//
// Math: diff-of-cumsums == cumsum-of-diffs, so per batch row:
//   carry = origin3 - origin2   (3 comps)
//   answer_row = |carry|_1 + sum_j | carry + prefix_j(Delta) |_1 , then /(N+1)
// Final: sum over rows.

#define NPTS   4095
#define NB     2048
#define BTH    512
#define ITEMS  8          // 512*8 = 4096 slots >= 4095 points

__device__ float g_partials[NB];

__device__ __forceinline__ float3 point_delta(
    float r3, float a3, float p3,   // 3D (already deformed) r, theta, phi
    float r2, float a2, float p2)   // 2D r, theta, phi
{
    float st3 = __sinf(a3), ct3 = __cosf(a3);
    float sp3 = __sinf(p3), cp3 = __cosf(p3);
    float st2 = __sinf(a2), ct2 = __cosf(a2);
    float sp2 = __sinf(p2), cp2 = __cosf(p2);
    float rs3 = r3 * st3;
    float rs2 = r2 * st2;
    float3 d;
    d.x = rs3 * cp3 - rs2 * cp2;
    d.y = rs3 * sp3 - rs2 * sp2;
    d.z = r3 * ct3 - r2 * ct2;
    return d;
}

__global__ void __launch_bounds__(BTH)
mpd_loss_main(const float* __restrict__ o3,
              const float* __restrict__ s3,
              const float* __restrict__ o2,
              const float* __restrict__ s2,
              const float* __restrict__ df)
{
    const int b    = blockIdx.x;
    const int t    = threadIdx.x;
    const int wid  = t >> 5;
    const int lane = t & 31;

    // Row pointers (contiguous in the point dim).
    const float* r3p  = s3 + (size_t)(b * 3) * NPTS;
    const float* th3p = r3p + NPTS;
    const float* ph3p = th3p + NPTS;
    const float* r2p  = s2 + (size_t)(b * 3) * NPTS;
    const float* th2p = r2p + NPTS;
    const float* ph2p = th2p + NPTS;
    const float* dthp = df + (size_t)(b * 2) * NPTS;
    const float* dphp = dthp + NPTS;

    // ---- Phase 1: coalesced loads + spherical->cart delta, strided layout ----
    float dxv[ITEMS], dyv[ITEMS], dzv[ITEMS];
#pragma unroll
    for (int i = 0; i < ITEMS; i++) {
        int j = i * BTH + t;
        float ddx = 0.f, ddy = 0.f, ddz = 0.f;
        if (j < NPTS) {
            float a3 = th3p[j] + dthp[j];
            float p3 = ph3p[j] + dphp[j];
            float3 d = point_delta(r3p[j], a3, p3, r2p[j], th2p[j], ph2p[j]);
            ddx = d.x; ddy = d.y; ddz = d.z;
        }
        dxv[i] = ddx; dyv[i] = ddy; dzv[i] = ddz;
    }

    // Carry = origin difference; j=0 term of per_pt is |carry|_1.
    float cx = o3[b * 3 + 0] - o2[b * 3 + 0];
    float cy = o3[b * 3 + 1] - o2[b * 3 + 1];
    float cz = o3[b * 3 + 2] - o2[b * 3 + 2];

    float acc = 0.f;
    if (t == 0) acc = fabsf(cx) + fabsf(cy) + fabsf(cz);

    __shared__ float wsx[16], wsy[16], wsz[16];

    // ---- Phase 2: 8 rounds of 512-wide block inclusive scan + |.|_1 accumulate ----
#pragma unroll
    for (int i = 0; i < ITEMS; i++) {
        float x = dxv[i], y = dyv[i], z = dzv[i];

        // warp-level inclusive scan
#pragma unroll
        for (int d = 1; d < 32; d <<= 1) {
            float ox = __shfl_up_sync(0xffffffffu, x, d);
            float oy = __shfl_up_sync(0xffffffffu, y, d);
            float oz = __shfl_up_sync(0xffffffffu, z, d);
            if (lane >= d) { x += ox; y += oy; z += oz; }
        }
        if (lane == 31) { wsx[wid] = x; wsy[wid] = y; wsz[wid] = z; }
        __syncthreads();

        // warp 0 lanes 0..15 scan the 16 warp totals (inclusive, in place)
        if (t < 16) {
            float vx = wsx[t], vy = wsy[t], vz = wsz[t];
#pragma unroll
            for (int d = 1; d < 16; d <<= 1) {
                float ox = __shfl_up_sync(0x0000ffffu, vx, d, 16);
                float oy = __shfl_up_sync(0x0000ffffu, vy, d, 16);
                float oz = __shfl_up_sync(0x0000ffffu, vz, d, 16);
                if (t >= d) { vx += ox; vy += oy; vz += oz; }
            }
            wsx[t] = vx; wsy[t] = vy; wsz[t] = vz;
        }
        __syncthreads();

        float offx = (wid > 0) ? wsx[wid - 1] : 0.f;
        float offy = (wid > 0) ? wsy[wid - 1] : 0.f;
        float offz = (wid > 0) ? wsz[wid - 1] : 0.f;

        float px = cx + offx + x;
        float py = cy + offy + y;
        float pz = cz + offz + z;

        int j = i * BTH + t;
        if (j < NPTS) acc += fabsf(px) + fabsf(py) + fabsf(pz);

        // carry += round total (broadcast of last inclusive warp-prefix)
        cx += wsx[15];
        cy += wsy[15];
        cz += wsz[15];
        __syncthreads();   // protect ws* before next round's writes
    }

    // ---- Phase 3: block reduce of acc ----
#pragma unroll
    for (int d = 16; d > 0; d >>= 1)
        acc += __shfl_down_sync(0xffffffffu, acc, d);
    if (lane == 0) wsx[wid] = acc;
    __syncthreads();
    if (t == 0) {
        float s = 0.f;
#pragma unroll
        for (int k = 0; k < 16; k++) s += wsx[k];
        g_partials[b] = s * (1.0f / (float)(NPTS + 1));
    }
}

__global__ void __launch_bounds__(1024)
mpd_loss_reduce(float* __restrict__ out)
{
    __shared__ float sm[1024];
    int t = threadIdx.x;
    float v = g_partials[t] + g_partials[t + 1024];
    sm[t] = v;
    __syncthreads();
#pragma unroll
    for (int s = 512; s > 0; s >>= 1) {
        if (t < s) sm[t] += sm[t + s];
        __syncthreads();
    }
    if (t == 0) out[0] = sm[0];
}

extern "C" void kernel_launch(void* const* d_in, const int* in_sizes, int n_in,
                              void* d_out, int out_size)
{
    (void)in_sizes; (void)n_in; (void)out_size;
    const float* o3 = (const float*)d_in[0];
    const float* s3 = (const float*)d_in[1];
    const float* o2 = (const float*)d_in[2];
    const float* s2 = (const float*)d_in[3];
    const float* df = (const float*)d_in[4];
    float* out = (float*)d_out;

    mpd_loss_main<<<NB, BTH>>>(o3, s3, o2, s2, df);
    mpd_loss_reduce<<<1, 1024>>>(out);
}

// round 5
// speedup vs baseline: 1.3349x; 1.3349x over previous
#include <cuda_runtime.h>
#include <math.h>

// B = 2048 rows, N = 4095 points/row.
// d_in[0] origin_3D (B,3,1), d_in[1] spherical_3D (B,3,N),
// d_in[2] origin_2D (B,3,1), d_in[3] spherical_2D (B,3,N),
// d_in[4] deformation_field (B,2,N). Output: scalar f32.
//
// diff-of-cumsums == cumsum-of-diffs:
//   carry = origin3 - origin2
//   row = |carry|_1 + sum_j |carry + prefix_j(Delta)|_1 ; row /= (N+1); out = sum rows.

#define NPTS   4095
#define NB     2048
#define BTH    512
#define ITEMS  8                    // 512*8 = 4096 slots
#define PADDED 4224                 // 4096 + 4096/32 pad
#define SMEMB  (3 * PADDED * 4)     // 50688 bytes dynamic smem

__device__ float        g_partials[NB];
__device__ unsigned int g_count = 0;

__global__ void __launch_bounds__(BTH)
mpd_loss_fused(const float* __restrict__ o3,
               const float* __restrict__ s3,
               const float* __restrict__ o2,
               const float* __restrict__ s2,
               const float* __restrict__ df,
               float* __restrict__ out)
{
    extern __shared__ float sm[];
    float* sxm = sm;
    float* sym = sm + PADDED;
    float* szm = sm + 2 * PADDED;

    const int b    = blockIdx.x;
    const int t    = threadIdx.x;
    const int wid  = t >> 5;
    const int lane = t & 31;

    const float* r3p  = s3 + (size_t)(b * 3) * NPTS;
    const float* th3p = r3p + NPTS;
    const float* ph3p = th3p + NPTS;
    const float* r2p  = s2 + (size_t)(b * 3) * NPTS;
    const float* th2p = r2p + NPTS;
    const float* ph2p = th2p + NPTS;
    const float* dthp = df + (size_t)(b * 2) * NPTS;
    const float* dphp = dthp + NPTS;

    // ---- Phase 1: strided coalesced loads + trig; deltas -> padded smem ----
#pragma unroll
    for (int i = 0; i < ITEMS; i++) {
        int j = i * BTH + t;
        float ddx = 0.f, ddy = 0.f, ddz = 0.f;
        if (j < NPTS) {
            float a3 = th3p[j] + dthp[j];
            float p3 = ph3p[j] + dphp[j];
            float r3 = r3p[j];
            float r2 = r2p[j];
            float a2 = th2p[j];
            float p2 = ph2p[j];
            float st3, ct3, sp3, cp3, st2, ct2, sp2, cp2;
            __sincosf(a3, &st3, &ct3);
            __sincosf(p3, &sp3, &cp3);
            __sincosf(a2, &st2, &ct2);
            __sincosf(p2, &sp2, &cp2);
            float rs3 = r3 * st3;
            float rs2 = r2 * st2;
            ddx = rs3 * cp3 - rs2 * cp2;
            ddy = rs3 * sp3 - rs2 * sp2;
            ddz = r3 * ct3 - r2 * ct2;
        }
        int p = j + (j >> 5);          // pad: conflict-free writes (contiguous per warp)
        sxm[p] = ddx; sym[p] = ddy; szm[p] = ddz;
    }

    float cx = o3[b * 3 + 0] - o2[b * 3 + 0];
    float cy = o3[b * 3 + 1] - o2[b * 3 + 1];
    float cz = o3[b * 3 + 2] - o2[b * 3 + 2];

    __syncthreads();

    // ---- Phase 2: per-thread serial prefix over 8 contiguous elems ----
    // element e = 8t+k  ->  padded index 8t + (t>>2) + k   (conflict-free reads)
    const int pb = t * ITEMS + (t >> 2);
    float px[ITEMS], py[ITEMS], pz[ITEMS];
    float ax = 0.f, ay = 0.f, az = 0.f;
#pragma unroll
    for (int k = 0; k < ITEMS; k++) {
        ax += sxm[pb + k]; px[k] = ax;
        ay += sym[pb + k]; py[k] = ay;
        az += szm[pb + k]; pz[k] = az;
    }

    // ---- single 512-wide block scan of thread totals (exclusive offsets) ----
    __shared__ float wsx[16], wsy[16], wsz[16];
    float ix = ax, iy = ay, iz = az;        // warp-inclusive scan values
#pragma unroll
    for (int d = 1; d < 32; d <<= 1) {
        float ox = __shfl_up_sync(0xffffffffu, ix, d);
        float oy = __shfl_up_sync(0xffffffffu, iy, d);
        float oz = __shfl_up_sync(0xffffffffu, iz, d);
        if (lane >= d) { ix += ox; iy += oy; iz += oz; }
    }
    if (lane == 31) { wsx[wid] = ix; wsy[wid] = iy; wsz[wid] = iz; }
    __syncthreads();
    if (t < 16) {
        float vx = wsx[t], vy = wsy[t], vz = wsz[t];
#pragma unroll
        for (int d = 1; d < 16; d <<= 1) {
            float ox = __shfl_up_sync(0x0000ffffu, vx, d, 16);
            float oy = __shfl_up_sync(0x0000ffffu, vy, d, 16);
            float oz = __shfl_up_sync(0x0000ffffu, vz, d, 16);
            if (t >= d) { vx += ox; vy += oy; vz += oz; }
        }
        wsx[t] = vx; wsy[t] = vy; wsz[t] = vz;
    }
    __syncthreads();

    float offx = cx + (wid ? wsx[wid - 1] : 0.f) + (ix - ax);   // exclusive prefix + carry
    float offy = cy + (wid ? wsy[wid - 1] : 0.f) + (iy - ay);
    float offz = cz + (wid ? wsz[wid - 1] : 0.f) + (iz - az);

    float acc = 0.f;
    if (t == 0) acc = fabsf(cx) + fabsf(cy) + fabsf(cz);        // j=0 origin term
#pragma unroll
    for (int k = 0; k < ITEMS; k++) {
        if (t * ITEMS + k < NPTS)
            acc += fabsf(offx + px[k]) + fabsf(offy + py[k]) + fabsf(offz + pz[k]);
    }

    // ---- block reduce acc ----
#pragma unroll
    for (int d = 16; d > 0; d >>= 1)
        acc += __shfl_down_sync(0xffffffffu, acc, d);
    if (lane == 0) wsx[wid] = acc;
    __syncthreads();

    __shared__ bool isLast;
    if (t == 0) {
        float s = 0.f;
#pragma unroll
        for (int k = 0; k < 16; k++) s += wsx[k];
        g_partials[b] = s * (1.0f / (float)(NPTS + 1));
        __threadfence();
        unsigned int c = atomicAdd(&g_count, 1u);
        isLast = (c == NB - 1);
    }
    __syncthreads();

    // ---- fused deterministic final reduction (last block) ----
    if (isLast) {
        float v = g_partials[t] + g_partials[t + 512] +
                  g_partials[t + 1024] + g_partials[t + 1536];
#pragma unroll
        for (int d = 16; d > 0; d >>= 1)
            v += __shfl_down_sync(0xffffffffu, v, d);
        if (lane == 0) wsy[wid] = v;
        __syncthreads();
        if (t == 0) {
            float s = 0.f;
#pragma unroll
            for (int k = 0; k < 16; k++) s += wsy[k];
            out[0] = s;
            g_count = 0;                  // reset for next graph replay
        }
    }
}

extern "C" void kernel_launch(void* const* d_in, const int* in_sizes, int n_in,
                              void* d_out, int out_size)
{
    (void)in_sizes; (void)n_in; (void)out_size;
    const float* o3 = (const float*)d_in[0];
    const float* s3 = (const float*)d_in[1];
    const float* o2 = (const float*)d_in[2];
    const float* s2 = (const float*)d_in[3];
    const float* df = (const float*)d_in[4];
    float* out = (float*)d_out;

    cudaFuncSetAttribute(mpd_loss_fused,
                         cudaFuncAttributeMaxDynamicSharedMemorySize, SMEMB);
    mpd_loss_fused<<<NB, BTH, SMEMB>>>(o3, s3, o2, s2, df, out);
}

// round 7
// speedup vs baseline: 1.4532x; 1.0886x over previous
#include <cuda_runtime.h>
#include <math.h>

// B = 2048 rows, N = 4095 points/row.
// d_in[0] origin_3D (B,3,1), d_in[1] spherical_3D (B,3,N),
// d_in[2] origin_2D (B,3,1), d_in[3] spherical_2D (B,3,N),
// d_in[4] deformation_field (B,2,N). Output: scalar f32.
//
// diff-of-cumsums == cumsum-of-diffs:
//   carry = origin3 - origin2
//   row = |carry|_1 + sum_j |carry + prefix_j(Delta)|_1 ; row /= (N+1); out = sum rows.

#define NPTS   4095
#define NB     2048
#define BTH    512
#define ITEMS  8                    // 512*8 = 4096 slots
#define PADDED 4224                 // 4096 + 4096/32 pad
#define SMEMB  (3 * PADDED * 4)     // 50688 bytes dynamic smem

__device__ float        g_partials[NB];
__device__ unsigned int g_count = 0;

__global__ void __launch_bounds__(BTH, 3)
mpd_loss_fused(const float* __restrict__ o3,
               const float* __restrict__ s3,
               const float* __restrict__ o2,
               const float* __restrict__ s2,
               const float* __restrict__ df,
               float* __restrict__ out)
{
    extern __shared__ float sm[];
    float* sxm = sm;
    float* sym = sm + PADDED;
    float* szm = sm + 2 * PADDED;

    const int b    = blockIdx.x;
    const int t    = threadIdx.x;
    const int wid  = t >> 5;
    const int lane = t & 31;

    const float* r3p  = s3 + (size_t)(b * 3) * NPTS;
    const float* th3p = r3p + NPTS;
    const float* ph3p = th3p + NPTS;
    const float* r2p  = s2 + (size_t)(b * 3) * NPTS;
    const float* th2p = r2p + NPTS;
    const float* ph2p = th2p + NPTS;
    const float* dthp = df + (size_t)(b * 2) * NPTS;
    const float* dphp = dthp + NPTS;

    // ---- Phase 1: strided coalesced loads + trig; deltas -> padded smem ----
#pragma unroll
    for (int i = 0; i < ITEMS; i++) {
        int j = i * BTH + t;
        float ddx = 0.f, ddy = 0.f, ddz = 0.f;
        if (j < NPTS) {
            float a3 = th3p[j] + dthp[j];
            float p3 = ph3p[j] + dphp[j];
            float r3 = r3p[j];
            float r2 = r2p[j];
            float a2 = th2p[j];
            float p2 = ph2p[j];
            float st3, ct3, sp3, cp3, st2, ct2, sp2, cp2;
            __sincosf(a3, &st3, &ct3);
            __sincosf(p3, &sp3, &cp3);
            __sincosf(a2, &st2, &ct2);
            __sincosf(p2, &sp2, &cp2);
            float rs3 = r3 * st3;
            float rs2 = r2 * st2;
            ddx = rs3 * cp3 - rs2 * cp2;
            ddy = rs3 * sp3 - rs2 * sp2;
            ddz = r3 * ct3 - r2 * ct2;
        }
        int p = j + (j >> 5);          // pad: conflict-free writes (contiguous per warp)
        sxm[p] = ddx; sym[p] = ddy; szm[p] = ddz;
    }

    float cx = o3[b * 3 + 0] - o2[b * 3 + 0];
    float cy = o3[b * 3 + 1] - o2[b * 3 + 1];
    float cz = o3[b * 3 + 2] - o2[b * 3 + 2];

    __syncthreads();

    // ---- Phase 2: per-thread serial totals over 8 contiguous elems ----
    // element e = 8t+k  ->  padded index 8t + (t>>2) + k   (conflict-free reads)
    const int pb = t * ITEMS + (t >> 2);
    float ax = 0.f, ay = 0.f, az = 0.f;
#pragma unroll
    for (int k = 0; k < ITEMS; k++) {
        ax += sxm[pb + k];
        ay += sym[pb + k];
        az += szm[pb + k];
    }

    // ---- single 512-wide block scan of thread totals ----
    __shared__ float wsx[16], wsy[16], wsz[16];
    float ix = ax, iy = ay, iz = az;        // warp-inclusive scan values
#pragma unroll
    for (int d = 1; d < 32; d <<= 1) {
        float ox = __shfl_up_sync(0xffffffffu, ix, d);
        float oy = __shfl_up_sync(0xffffffffu, iy, d);
        float oz = __shfl_up_sync(0xffffffffu, iz, d);
        if (lane >= d) { ix += ox; iy += oy; iz += oz; }
    }
    if (lane == 31) { wsx[wid] = ix; wsy[wid] = iy; wsz[wid] = iz; }
    __syncthreads();
    if (t < 16) {
        float vx = wsx[t], vy = wsy[t], vz = wsz[t];
#pragma unroll
        for (int d = 1; d < 16; d <<= 1) {
            float ox = __shfl_up_sync(0x0000ffffu, vx, d, 16);
            float oy = __shfl_up_sync(0x0000ffffu, vy, d, 16);
            float oz = __shfl_up_sync(0x0000ffffu, vz, d, 16);
            if (t >= d) { vx += ox; vy += oy; vz += oz; }
        }
        wsx[t] = vx; wsy[t] = vy; wsz[t] = vz;
    }
    __syncthreads();

    // exclusive thread offset + origin carry
    float rx = cx + (wid ? wsx[wid - 1] : 0.f) + (ix - ax);
    float ry = cy + (wid ? wsy[wid - 1] : 0.f) + (iy - ay);
    float rz = cz + (wid ? wsz[wid - 1] : 0.f) + (iz - az);

    // ---- Phase 3: re-read deltas, running prefix + |.|_1 accumulate ----
    float acc = 0.f;
    if (t == 0) acc = fabsf(cx) + fabsf(cy) + fabsf(cz);        // j=0 origin term
#pragma unroll
    for (int k = 0; k < ITEMS; k++) {
        rx += sxm[pb + k];
        ry += sym[pb + k];
        rz += szm[pb + k];
        if (t * ITEMS + k < NPTS)
            acc += fabsf(rx) + fabsf(ry) + fabsf(rz);
    }

    // ---- block reduce acc ----
#pragma unroll
    for (int d = 16; d > 0; d >>= 1)
        acc += __shfl_down_sync(0xffffffffu, acc, d);
    if (lane == 0) wsx[wid] = acc;
    __syncthreads();

    __shared__ bool isLast;
    if (t == 0) {
        float s = 0.f;
#pragma unroll
        for (int k = 0; k < 16; k++) s += wsx[k];
        g_partials[b] = s * (1.0f / (float)(NPTS + 1));
        __threadfence();
        unsigned int c = atomicAdd(&g_count, 1u);
        isLast = (c == NB - 1);
    }
    __syncthreads();

    // ---- fused deterministic final reduction (last block) ----
    if (isLast) {
        float v = g_partials[t] + g_partials[t + 512] +
                  g_partials[t + 1024] + g_partials[t + 1536];
#pragma unroll
        for (int d = 16; d > 0; d >>= 1)
            v += __shfl_down_sync(0xffffffffu, v, d);
        if (lane == 0) wsy[wid] = v;
        __syncthreads();
        if (t == 0) {
            float s = 0.f;
#pragma unroll
            for (int k = 0; k < 16; k++) s += wsy[k];
            out[0] = s;
            g_count = 0;                  // reset for next graph replay
        }
    }
}

extern "C" void kernel_launch(void* const* d_in, const int* in_sizes, int n_in,
                              void* d_out, int out_size)
{
    (void)in_sizes; (void)n_in; (void)out_size;
    const float* o3 = (const float*)d_in[0];
    const float* s3 = (const float*)d_in[1];
    const float* o2 = (const float*)d_in[2];
    const float* s2 = (const float*)d_in[3];
    const float* df = (const float*)d_in[4];
    float* out = (float*)d_out;

    cudaFuncSetAttribute(mpd_loss_fused,
                         cudaFuncAttributeMaxDynamicSharedMemorySize, SMEMB);
    mpd_loss_fused<<<NB, BTH, SMEMB>>>(o3, s3, o2, s2, df, out);
}